// round 2
// baseline (speedup 1.0000x reference)
#include <cuda_runtime.h>
#include <cuda_bf16.h>
#include <cstdint>

// ---------------------------------------------------------------------------
// CharRNN: T=16384 LSTM steps, E=H=1024, loss = sum_t (logsumexp(h_t) - h_t[y_t])
//
// Kernel 0: init barrier state (makes the persistent kernel replay-safe)
// Kernel 1: xg[T][4H] = Xs @ W_ih^T + (b_ih + b_hh)    (fp32 tiled GEMM)
// Kernel 2: persistent grid kernel; 128 work CTAs (each warp owns one h index
//           and its 4 gate rows of W_hh in registers) + 1 loss CTA.
//           One global spin barrier per timestep, double-buffered h.
// ---------------------------------------------------------------------------

#define T_STEPS 16384
#define E_DIM   1024
#define H_DIM   1024
#define NWORK   128
#define NCTA    129     // 128 work + 1 loss

// scratch (static device allocs are allowed)
__device__ float     g_xg[(size_t)T_STEPS * 4 * H_DIM];   // 256 MB
__device__ float     g_hbuf[2][H_DIM];
__device__ unsigned  g_cnt[2];
__device__ unsigned  g_gen;

// ---------------------------------------------------------------------------
__global__ void init_kernel()
{
    g_cnt[0] = 0u;
    g_cnt[1] = 0u;
    g_gen    = 0u;
}

// ---------------------------------------------------------------------------
// GEMM: C[M=T][N=4096] = X[M][K=1024] * W[N][K]^T + (b1+b2)
// 128x128 tile, BK=8, 256 threads, 8x8 per-thread tile.
// ---------------------------------------------------------------------------
__global__ __launch_bounds__(256, 2) void xg_gemm_kernel(
    const float* __restrict__ X, const float* __restrict__ W,
    const float* __restrict__ b1, const float* __restrict__ b2)
{
    __shared__ float As[8][128];
    __shared__ float Bs[8][128];

    const int bm = blockIdx.y * 128;
    const int bn = blockIdx.x * 128;
    const int tid = threadIdx.x;
    const int tr = (tid >> 4) << 3;      // 0..120 step 8
    const int tc = (tid & 15) << 3;      // 0..120 step 8
    const int lr = tid >> 1;             // 0..127
    const int lc = (tid & 1) << 2;       // 0 or 4

    const float* Ag = X + (size_t)(bm + lr) * E_DIM + lc;
    const float* Bg = W + (size_t)(bn + lr) * E_DIM + lc;

    float acc[8][8];
#pragma unroll
    for (int i = 0; i < 8; i++)
#pragma unroll
        for (int j = 0; j < 8; j++) acc[i][j] = 0.f;

    for (int k0 = 0; k0 < E_DIM; k0 += 8) {
        float4 av = *(const float4*)(Ag + k0);
        float4 bv = *(const float4*)(Bg + k0);
        __syncthreads();   // previous tile's compute done
        As[lc + 0][lr] = av.x; As[lc + 1][lr] = av.y;
        As[lc + 2][lr] = av.z; As[lc + 3][lr] = av.w;
        Bs[lc + 0][lr] = bv.x; Bs[lc + 1][lr] = bv.y;
        Bs[lc + 2][lr] = bv.z; Bs[lc + 3][lr] = bv.w;
        __syncthreads();
#pragma unroll
        for (int kk = 0; kk < 8; kk++) {
            float a[8], b[8];
#pragma unroll
            for (int i = 0; i < 8; i++) a[i] = As[kk][tr + i];
#pragma unroll
            for (int j = 0; j < 8; j++) b[j] = Bs[kk][tc + j];
#pragma unroll
            for (int i = 0; i < 8; i++)
#pragma unroll
                for (int j = 0; j < 8; j++)
                    acc[i][j] = fmaf(a[i], b[j], acc[i][j]);
        }
    }

    float bias[8];
#pragma unroll
    for (int j = 0; j < 8; j++) bias[j] = b1[bn + tc + j] + b2[bn + tc + j];

#pragma unroll
    for (int i = 0; i < 8; i++) {
        size_t row = (size_t)(bm + tr + i);
        float* cp = g_xg + row * (4 * H_DIM) + bn + tc;
        float4 v0, v1;
        v0.x = acc[i][0] + bias[0]; v0.y = acc[i][1] + bias[1];
        v0.z = acc[i][2] + bias[2]; v0.w = acc[i][3] + bias[3];
        v1.x = acc[i][4] + bias[4]; v1.y = acc[i][5] + bias[5];
        v1.z = acc[i][6] + bias[6]; v1.w = acc[i][7] + bias[7];
        *(float4*)(cp + 0) = v0;
        *(float4*)(cp + 4) = v1;
    }
}

// ---------------------------------------------------------------------------
// grid barrier. g_cnt/g_gen are zeroed by init_kernel before this launch,
// counters self-reset (cnt[t&1] reused at t+2), so replay-safe with no
// per-CTA generation sampling (that was racy).
// ---------------------------------------------------------------------------
__device__ __forceinline__ void grid_barrier(int t)
{
    __syncthreads();
    if (threadIdx.x == 0) {
        __threadfence();                       // release h writes
        unsigned old = atomicAdd(&g_cnt[t & 1], 1u);
        if (old == (unsigned)(NCTA - 1)) {
            atomicExch(&g_cnt[t & 1], 0u);     // reset for reuse at t+2
            __threadfence();
            atomicAdd(&g_gen, 1u);
        } else {
            while (*(volatile unsigned*)&g_gen < (unsigned)(t + 1)) { }
            __threadfence();                   // acquire
        }
    }
    __syncthreads();
}

__device__ __forceinline__ float fast_sigmoid(float x)
{
    return __fdividef(1.f, 1.f + __expf(-x));
}
__device__ __forceinline__ float fast_tanh(float x)
{
    float e = __expf(-2.f * fabsf(x));
    float r = __fdividef(1.f - e, 1.f + e);
    return copysignf(r, x);
}

// ---------------------------------------------------------------------------
// persistent LSTM kernel: 129 CTAs x 256 threads
// ---------------------------------------------------------------------------
__global__ __launch_bounds__(256, 1) void lstm_kernel(
    const float* __restrict__ W_hh,
    const int* __restrict__ ys32,     // raw words of ys; dtype detected at runtime
    float* __restrict__ out)
{
    const int cta = blockIdx.x;
    const int tid = threadIdx.x;

    if (cta < NWORK) {
        // ---------------- work CTA ----------------
        __shared__ float hs[H_DIM];           // staged previous h
        const int warp = tid >> 5;
        const int lane = tid & 31;
        const int k = cta * 8 + warp;         // owned h index

        // rows k, H+k, 2H+k, 3H+k of W_hh; lane holds float4 columns
        const float4* Wv = (const float4*)W_hh;     // row stride = 256 float4
        float4 w0[8], w1[8], w2[8], w3[8];
#pragma unroll
        for (int c = 0; c < 8; c++) {
            int col = lane + 32 * c;
            w0[c] = Wv[(size_t)(0 * H_DIM + k) * 256 + col];
            w1[c] = Wv[(size_t)(1 * H_DIM + k) * 256 + col];
            w2[c] = Wv[(size_t)(2 * H_DIM + k) * 256 + col];
            w3[c] = Wv[(size_t)(3 * H_DIM + k) * 256 + col];
        }

        float c_state = 0.f;
        float4* hs4 = (float4*)hs;

        for (int t = 0; t < T_STEPS; t++) {
            // stage previous h into SMEM (one float4 per thread)
            if (t > 0) {
                const float4* hb = (const float4*)g_hbuf[t & 1];
                hs4[tid] = __ldcg(hb + tid);
            }

            // xg gates for this step (lane 0 only)
            float xgi = 0.f, xgf = 0.f, xgg = 0.f, xgo = 0.f;
            if (lane == 0) {
                const float* xr = g_xg + (size_t)t * (4 * H_DIM);
                xgi = __ldcs(xr + 0 * H_DIM + k);
                xgf = __ldcs(xr + 1 * H_DIM + k);
                xgg = __ldcs(xr + 2 * H_DIM + k);
                xgo = __ldcs(xr + 3 * H_DIM + k);
            }

            float a0 = 0.f, a1 = 0.f, a2 = 0.f, a3 = 0.f;
            if (t > 0) {
                __syncthreads();              // hs ready
#pragma unroll
                for (int c = 0; c < 8; c++) {
                    float4 hv = hs4[lane + 32 * c];
                    a0 = fmaf(w0[c].x, hv.x, a0); a0 = fmaf(w0[c].y, hv.y, a0);
                    a0 = fmaf(w0[c].z, hv.z, a0); a0 = fmaf(w0[c].w, hv.w, a0);
                    a1 = fmaf(w1[c].x, hv.x, a1); a1 = fmaf(w1[c].y, hv.y, a1);
                    a1 = fmaf(w1[c].z, hv.z, a1); a1 = fmaf(w1[c].w, hv.w, a1);
                    a2 = fmaf(w2[c].x, hv.x, a2); a2 = fmaf(w2[c].y, hv.y, a2);
                    a2 = fmaf(w2[c].z, hv.z, a2); a2 = fmaf(w2[c].w, hv.w, a2);
                    a3 = fmaf(w3[c].x, hv.x, a3); a3 = fmaf(w3[c].y, hv.y, a3);
                    a3 = fmaf(w3[c].z, hv.z, a3); a3 = fmaf(w3[c].w, hv.w, a3);
                }
            }

            // warp reduce the 4 partial dots
#pragma unroll
            for (int off = 16; off; off >>= 1) {
                a0 += __shfl_xor_sync(0xffffffffu, a0, off);
                a1 += __shfl_xor_sync(0xffffffffu, a1, off);
                a2 += __shfl_xor_sync(0xffffffffu, a2, off);
                a3 += __shfl_xor_sync(0xffffffffu, a3, off);
            }

            if (lane == 0) {
                float gi = fast_sigmoid(a0 + xgi);
                float gf = fast_sigmoid(a1 + xgf);
                float gg = fast_tanh(a2 + xgg);
                float go = fast_sigmoid(a3 + xgo);
                c_state = gf * c_state + gi * gg;
                float h = go * fast_tanh(c_state);
                __stcg(&g_hbuf[(t + 1) & 1][k], h);
            }

            grid_barrier(t);
        }
    } else {
        // ---------------- loss CTA ----------------
        __shared__ float red[8];
        __shared__ int   s_is64;
        const int warp = tid >> 5;
        const int lane = tid & 31;

        // --- detect ys dtype. Scan first 16384 int32 words (in-bounds for
        // both int32[16384] and int64[16384] buffers). If int64: labels<1024
        // so every odd word is 0. If any odd word != 0 -> int32. ---
        if (tid == 0) s_is64 = 1;
        __syncthreads();
        {
            int odd_nonzero = 0;
            for (int i = tid; i < T_STEPS / 2; i += 256)
                odd_nonzero |= (ys32[2 * i + 1] != 0);
            if (odd_nonzero) s_is64 = 0;   // benign race: all writers write 0
        }
        __syncthreads();
        const int is64 = s_is64;

        double acc = 0.0;

        for (int t = 0; t <= T_STEPS; t++) {
            if (t > 0) {
                const float4* hb = (const float4*)g_hbuf[t & 1];
                float4 hv = __ldcg(hb + tid);
                float s = __expf(hv.x) + __expf(hv.y) + __expf(hv.z) + __expf(hv.w);
#pragma unroll
                for (int off = 16; off; off >>= 1)
                    s += __shfl_xor_sync(0xffffffffu, s, off);
                if (lane == 0) red[warp] = s;
                __syncthreads();
                if (tid == 0) {
                    float tot = 0.f;
#pragma unroll
                    for (int i = 0; i < 8; i++) tot += red[i];
                    int y = is64 ? ys32[2 * (t - 1)] : ys32[t - 1];
                    y &= (H_DIM - 1);   // never fault even on mis-detect
                    float hy = __ldcg(&g_hbuf[t & 1][y]);
                    acc += (double)(logf(tot) - hy);
                }
                __syncthreads();
            }
            if (t < T_STEPS) grid_barrier(t);
        }
        if (tid == 0) out[0] = (float)acc;
    }
}

// ---------------------------------------------------------------------------
extern "C" void kernel_launch(void* const* d_in, const int* in_sizes, int n_in,
                              void* d_out, int out_size)
{
    const float* Xs   = (const float*)d_in[0];
    const float* W_ih = (const float*)d_in[1];
    const float* W_hh = (const float*)d_in[2];
    const float* b_ih = (const float*)d_in[3];
    const float* b_hh = (const float*)d_in[4];
    const int*   ys32 = (const int*)d_in[5];
    float* out = (float*)d_out;

    (void)in_sizes; (void)n_in; (void)out_size;

    init_kernel<<<1, 1>>>();
    dim3 ggrid(4 * H_DIM / 128, T_STEPS / 128);   // (32, 128)
    xg_gemm_kernel<<<ggrid, 256>>>(Xs, W_ih, b_ih, b_hh);
    lstm_kernel<<<NCTA, 256>>>(W_hh, ys32, out);
}